// round 1
// baseline (speedup 1.0000x reference)
#include <cuda_runtime.h>
#include <math.h>

// ArcFace fused loss. N=512, D=512, C=100000.
// Pipeline:
//   1) norm_x:   x_hat = x / max(||x||, 1e-12)   (also zeroes per-row sum accumulators)
//   2) wnorm:    rnorm_c = 1 / max(||w_c||, 1e-12)
//   3) gemm:     128x128 fp32 SIMT tile GEMM over K=512, epilogue applies
//                clip/margin and accumulates sum_c exp(logit - 64) per row +
//                records the target logit.
//   4) finalize: mean_i [ log(rowsum_i) + 64 - target_logit_i ]  -> d_out[0]

#define N_ 512
#define D_ 512
#define C_ 100000

#define SCALE_   64.0f
#define CLIP_LO  (-1.0f + 1e-7f)
#define CLIP_HI  (1.0f - 1e-7f)
#define COS_M_   0.8775825618903728f   // cos(0.5)
#define SIN_M_   0.4794255386042030f   // sin(0.5)
#define TH_      (-0.8775825618903728f) // cos(pi - 0.5)
#define MM_      0.2397127693021015f   // sin(pi - 0.5) * 0.5

__device__ float g_xn[N_ * D_];     // normalized input
__device__ float g_wrn[C_];         // 1/||w_c||
__device__ float g_rowsum[N_];      // sum_c exp(logit - 64)
__device__ float g_tlogit[N_];      // target logit per row

// ---------------------------------------------------------------------------
// 1) normalize input rows; zero row sums
// ---------------------------------------------------------------------------
__global__ void norm_x_kernel(const float* __restrict__ x) {
    int row = blockIdx.x;            // 512 blocks
    int tid = threadIdx.x;           // 128 threads, 4 floats each
    if (tid == 0) g_rowsum[row] = 0.0f;

    float4 v = *(const float4*)(x + (size_t)row * D_ + tid * 4);
    float ss = v.x * v.x + v.y * v.y + v.z * v.z + v.w * v.w;
    #pragma unroll
    for (int o = 16; o; o >>= 1) ss += __shfl_xor_sync(0xffffffffu, ss, o);

    __shared__ float sm[4];
    if ((tid & 31) == 0) sm[tid >> 5] = ss;
    __syncthreads();
    float tot = sm[0] + sm[1] + sm[2] + sm[3];
    float inv = 1.0f / fmaxf(sqrtf(tot), 1e-12f);

    float4 o4;
    o4.x = v.x * inv; o4.y = v.y * inv; o4.z = v.z * inv; o4.w = v.w * inv;
    *(float4*)(g_xn + (size_t)row * D_ + tid * 4) = o4;
}

// ---------------------------------------------------------------------------
// 2) weight row inverse norms (one warp per class row)
// ---------------------------------------------------------------------------
__global__ void wnorm_kernel(const float* __restrict__ w, int C) {
    int warp = (blockIdx.x * blockDim.x + threadIdx.x) >> 5;
    int lane = threadIdx.x & 31;
    if (warp >= C) return;
    const float* p = w + (size_t)warp * D_;
    float ss = 0.0f;
    #pragma unroll
    for (int q = 0; q < 4; q++) {
        float4 v = *(const float4*)(p + lane * 4 + q * 128);
        ss += v.x * v.x + v.y * v.y + v.z * v.z + v.w * v.w;
    }
    #pragma unroll
    for (int o = 16; o; o >>= 1) ss += __shfl_xor_sync(0xffffffffu, ss, o);
    if (lane == 0) g_wrn[warp] = 1.0f / fmaxf(sqrtf(ss), 1e-12f);
}

// ---------------------------------------------------------------------------
// 3) tiled GEMM + ArcFace epilogue + online sum-of-exp
//    BM=128 (rows of x), BN=128 (classes), BK=16, 256 threads, 8x8/thread
// ---------------------------------------------------------------------------
__global__ void __launch_bounds__(256, 2)
arcface_gemm_kernel(const float* __restrict__ w,
                    const int* __restrict__ target, int C) {
    __shared__ float As[16][132];   // [k][m], padded pitch to break store conflicts
    __shared__ float Bs[16][132];   // [k][n]

    int tid = threadIdx.x;
    int m0 = blockIdx.x * 128;      // grid.x = 4  (M-tiles adjacent -> weight tile L2 reuse)
    int c0 = blockIdx.y * 128;      // grid.y = 782
    int tx = tid & 15;
    int ty = tid >> 4;
    int lrow = tid >> 2;            // 0..63
    int lf   = tid & 3;             // which float4 along k

    float acc[8][8];
    #pragma unroll
    for (int i = 0; i < 8; i++)
        #pragma unroll
        for (int j = 0; j < 8; j++) acc[i][j] = 0.0f;

    for (int k0 = 0; k0 < D_; k0 += 16) {
        #pragma unroll
        for (int it = 0; it < 2; it++) {
            int r = lrow + it * 64;
            float4 av = *(const float4*)(g_xn + (size_t)(m0 + r) * D_ + k0 + lf * 4);
            As[lf * 4 + 0][r] = av.x;
            As[lf * 4 + 1][r] = av.y;
            As[lf * 4 + 2][r] = av.z;
            As[lf * 4 + 3][r] = av.w;

            int c = c0 + r;
            float4 bv = make_float4(0.f, 0.f, 0.f, 0.f);
            if (c < C)
                bv = *(const float4*)(w + (size_t)c * D_ + k0 + lf * 4);
            Bs[lf * 4 + 0][r] = bv.x;
            Bs[lf * 4 + 1][r] = bv.y;
            Bs[lf * 4 + 2][r] = bv.z;
            Bs[lf * 4 + 3][r] = bv.w;
        }
        __syncthreads();

        #pragma unroll
        for (int k = 0; k < 16; k++) {
            float a[8], b[8];
            *(float4*)&a[0] = *(const float4*)&As[k][ty * 4];
            *(float4*)&a[4] = *(const float4*)&As[k][64 + ty * 4];
            *(float4*)&b[0] = *(const float4*)&Bs[k][tx * 4];
            *(float4*)&b[4] = *(const float4*)&Bs[k][64 + tx * 4];
            #pragma unroll
            for (int i = 0; i < 8; i++)
                #pragma unroll
                for (int j = 0; j < 8; j++)
                    acc[i][j] += a[i] * b[j];
        }
        __syncthreads();
    }

    // --- epilogue: clip, margin on target column, sum exp(logit - 64) per row
    #pragma unroll
    for (int i = 0; i < 8; i++) {
        int rm = (i < 4) ? (ty * 4 + i) : (64 + ty * 4 + (i - 4));
        int gm = m0 + rm;
        int tgt = target[gm];
        float p = 0.0f;
        #pragma unroll
        for (int j = 0; j < 8; j++) {
            int cn = (j < 4) ? (tx * 4 + j) : (64 + tx * 4 + (j - 4));
            int gc = c0 + cn;
            if (gc < C) {
                float cosv = acc[i][j] * g_wrn[gc];
                cosv = fminf(fmaxf(cosv, CLIP_LO), CLIP_HI);
                float logit;
                if (gc == tgt) {
                    float t = 1.0f - cosv * cosv;
                    t = fminf(fmaxf(t, CLIP_LO), CLIP_HI);
                    float sine = sqrtf(t);
                    float phi = cosv * COS_M_ - sine * SIN_M_;
                    if (!(cosv > TH_)) phi = cosv - MM_;
                    logit = phi * SCALE_;
                    g_tlogit[gm] = logit;   // exactly one writer per row
                } else {
                    logit = cosv * SCALE_;
                }
                p += __expf(logit - 64.0f);
            }
        }
        // reduce across the 16 tx lanes (width-16 segments inside the warp)
        #pragma unroll
        for (int o = 8; o; o >>= 1)
            p += __shfl_down_sync(0xffffffffu, p, o, 16);
        if (tx == 0)
            atomicAdd(&g_rowsum[gm], p);
    }
}

// ---------------------------------------------------------------------------
// 4) finalize: mean NLL
// ---------------------------------------------------------------------------
__global__ void finalize_kernel(float* __restrict__ out) {
    int i = threadIdx.x;  // 512
    float v = (logf(g_rowsum[i]) + 64.0f) - g_tlogit[i];
    #pragma unroll
    for (int o = 16; o; o >>= 1) v += __shfl_xor_sync(0xffffffffu, v, o);
    __shared__ float sm[16];
    if ((i & 31) == 0) sm[i >> 5] = v;
    __syncthreads();
    if (i < 16) {
        float t = sm[i];
        #pragma unroll
        for (int o = 8; o; o >>= 1) t += __shfl_xor_sync(0x0000ffffu, t, o);
        if (i == 0) out[0] = t * (1.0f / (float)N_);
    }
}

// ---------------------------------------------------------------------------
extern "C" void kernel_launch(void* const* d_in, const int* in_sizes, int n_in,
                              void* d_out, int out_size) {
    const float* x   = (const float*)d_in[0];   // [512, 512] fp32
    const int*   tgt = (const int*)d_in[1];     // [512] (jax x64 off -> int32)
    const float* w   = (const float*)d_in[2];   // [100000, 512] fp32

    norm_x_kernel<<<N_, 128>>>(x);
    wnorm_kernel<<<(C_ + 7) / 8, 256>>>(w, C_);
    dim3 grid(4, (C_ + 127) / 128);
    arcface_gemm_kernel<<<grid, 256>>>(w, tgt, C_);
    finalize_kernel<<<1, N_>>>((float*)d_out);
}